// round 3
// baseline (speedup 1.0000x reference)
#include <cuda_runtime.h>

// GRU persistent kernel, fp32 CUDA-core baseline.
// B=128, T=1024, I=256, H=512. Grid = 128 CTAs (4 batch tiles x 32 j tiles),
// 256 threads each, single wave => software grid barrier is safe.

#define BB 128
#define TT 1024
#define II 256
#define HH 512

#define BM 32          // batch rows per CTA
#define BJ 16          // j columns per CTA
#define NROWS 48       // 3 gates * BJ weight rows per CTA
#define KTOT 768       // II + HH
#define KC 128         // k-chunk staged in SMEM
#define WST 772        // padded W row stride (floats)
#define VST 132        // padded V row stride (floats)
#define NTHREADS 256
#define GRID 128

// Scratch state (device globals: no allocations allowed in kernel_launch)
__device__ float g_hbuf[2][BB * HH];
__device__ int g_count;            // barrier arrival counter (reset each launch)
__device__ volatile int g_flag;    // barrier release phase   (reset each launch)

__global__ void __launch_bounds__(NTHREADS, 1) gru_persistent(
    const float* __restrict__ x,    // (B, T, I)
    const float* __restrict__ h0,   // (1, B, H)
    const float* __restrict__ Wih,  // (3H, I)
    const float* __restrict__ bih,  // (3H)
    const float* __restrict__ Whh,  // (3H, H)
    const float* __restrict__ bhh,  // (3H)
    float* __restrict__ out)        // (B,1,4H) then (1,B,4H) concatenated
{
    extern __shared__ float smem[];
    float* Wt = smem;                    // [NROWS][WST]  resident weights
    float* Vt = smem + NROWS * WST;      // [BM][VST]     staged input chunk

    const int cta = blockIdx.x;
    const int cm  = cta & 3;             // batch tile 0..3
    const int cn  = cta >> 2;            // j tile 0..31
    const int bm0 = cm * BM;
    const int j0  = cn * BJ;
    const int tid = threadIdx.x;
    const int tx  = tid & 15;            // j_local
    const int ty  = tid >> 4;            // m pair index
    const int m0  = 2 * ty;
    const int m1  = 2 * ty + 1;
    const int j   = j0 + tx;

    // ---- Load weight slice into SMEM once (rows: gate*16 + j_local) ----
    for (int idx = tid; idx < NROWS * KTOT; idx += NTHREADS) {
        int row = idx / KTOT;
        int k   = idx - row * KTOT;
        int g   = (row >> 4) * HH + j0 + (row & 15);   // global gate row
        float v = (k < II) ? Wih[g * II + k] : Whh[g * HH + (k - II)];
        Wt[row * WST + k] = v;
    }

    // Per-thread constant biases for column j
    const float rb  = bih[j]          + bhh[j];
    const float zb  = bih[HH + j]     + bhh[HH + j];
    const float nbi = bih[2 * HH + j];
    const float nbh = bhh[2 * HH + j];
    __syncthreads();

#define STAGE(SRCEXPR)                                                   \
    __syncthreads();                                                     \
    {                                                                    \
        _Pragma("unroll")                                                \
        for (int q = tid; q < BM * (KC / 4); q += NTHREADS) {            \
            int m  = q >> 5;                                             \
            int kf = q & 31;                                             \
            float4 val = (SRCEXPR);                                      \
            *(float4*)(Vt + m * VST + kf * 4) = val;                     \
        }                                                                \
    }                                                                    \
    __syncthreads();

#define COMPUTE(ACC, KBASE)                                              \
    {                                                                    \
        _Pragma("unroll 8")                                              \
        for (int ks = 0; ks < KC; ks += 4) {                             \
            float4 va = *(const float4*)(Vt + m0 * VST + ks);            \
            float4 vb = *(const float4*)(Vt + m1 * VST + ks);            \
            const float* wb = Wt + (KBASE) + ks;                         \
            float4 w0 = *(const float4*)(wb + (tx)      * WST);          \
            float4 w1 = *(const float4*)(wb + (tx + 16) * WST);          \
            float4 w2 = *(const float4*)(wb + (tx + 32) * WST);          \
            ACC[0][0] += va.x*w0.x + va.y*w0.y + va.z*w0.z + va.w*w0.w;  \
            ACC[0][1] += va.x*w1.x + va.y*w1.y + va.z*w1.z + va.w*w1.w;  \
            ACC[0][2] += va.x*w2.x + va.y*w2.y + va.z*w2.z + va.w*w2.w;  \
            ACC[1][0] += vb.x*w0.x + vb.y*w0.y + vb.z*w0.z + vb.w*w0.w;  \
            ACC[1][1] += vb.x*w1.x + vb.y*w1.y + vb.z*w1.z + vb.w*w1.w;  \
            ACC[1][2] += vb.x*w2.x + vb.y*w2.y + vb.z*w2.z + vb.w*w2.w;  \
        }                                                                \
    }

    for (int t = 0; t < TT; t++) {
        const float* hread  = (t == 0) ? h0 : g_hbuf[(t - 1) & 1];
        float*       hwrite = g_hbuf[t & 1];

        float aX[2][3] = {{0.f,0.f,0.f},{0.f,0.f,0.f}};
        float aH[2][3] = {{0.f,0.f,0.f},{0.f,0.f,0.f}};

        const float hp0 = hread[(bm0 + m0) * HH + j];
        const float hp1 = hread[(bm0 + m1) * HH + j];

        // x phase: k in [0, 256)
        #pragma unroll
        for (int kc = 0; kc < 2; kc++) {
            STAGE(*(const float4*)(x + ((size_t)(bm0 + m) * TT + t) * II
                                     + kc * KC + kf * 4))
            COMPUTE(aX, kc * KC)
        }
        // h phase: k in [0, 512)
        #pragma unroll
        for (int kc = 0; kc < 4; kc++) {
            STAGE(*(const float4*)(hread + (size_t)(bm0 + m) * HH
                                         + kc * KC + kf * 4))
            COMPUTE(aH, II + kc * KC)
        }

        // ---- Gates (fully in-register; thread owns r,z,n for (b, j)) ----
        #pragma unroll
        for (int mi = 0; mi < 2; mi++) {
            const int   b  = bm0 + m0 + mi;
            const float hp = mi ? hp1 : hp0;
            float r  = 1.f / (1.f + __expf(-(aX[mi][0] + aH[mi][0] + rb)));
            float z  = 1.f / (1.f + __expf(-(aX[mi][1] + aH[mi][1] + zb)));
            float nn = tanhf(aX[mi][2] + nbi + r * (aH[mi][2] + nbh));
            float hn = (1.f - z) * nn + z * hp;
            hwrite[b * HH + j] = hn;
            if (t == TT - 1) {
                int o  = b * (4 * HH) + j;
                int o2 = o + BB * 4 * HH;
                out[o]            = r;  out[o2]            = r;
                out[o + HH]       = z;  out[o2 + HH]       = z;
                out[o + 2 * HH]   = nn; out[o2 + 2 * HH]   = nn;
                out[o + 3 * HH]   = hn; out[o2 + 3 * HH]   = hn;
            }
        }

        // ---- Grid barrier (flag/counter; single-wave residency) ----
        if (t < TT - 1) {
            __threadfence();
            __syncthreads();
            if (tid == 0) {
                int old = atomicAdd(&g_count, 1);
                if (old == GRID - 1) {
                    g_count = 0;
                    __threadfence();
                    g_flag = t + 1;
                } else {
                    while (g_flag < t + 1) { }
                    __threadfence();
                }
            }
            __syncthreads();
        }
    }

    // ---- Cleanup barrier state for the next launch (no spin) ----
    __syncthreads();
    if (tid == 0) {
        int old = atomicAdd(&g_count, 1);
        if (old == GRID - 1) {
            g_count = 0;
            g_flag  = 0;
            __threadfence();
        }
    }
}

extern "C" void kernel_launch(void* const* d_in, const int* in_sizes, int n_in,
                              void* d_out, int out_size) {
    const float* x   = (const float*)d_in[0];
    const float* h   = (const float*)d_in[1];
    const float* Wih = (const float*)d_in[2];
    const float* bih = (const float*)d_in[3];
    const float* Whh = (const float*)d_in[4];
    const float* bhh = (const float*)d_in[5];
    float* out = (float*)d_out;

    const int smem_bytes = (NROWS * WST + BM * VST) * 4;
    cudaFuncSetAttribute(gru_persistent,
                         cudaFuncAttributeMaxDynamicSharedMemorySize,
                         smem_bytes);
    gru_persistent<<<GRID, NTHREADS, smem_bytes>>>(x, h, Wih, bih, Whh, bhh, out);
}